// round 3
// baseline (speedup 1.0000x reference)
#include <cuda_runtime.h>

#define NWARM 365

// PARAM_RANGES lo/hi, order: KC,PCTIM,ADIMP,UZTWM,UZFWM,LZTWM,LZFSM,LZFPM,RSERV,
// PFREE,RIVA,ZPERC,REXP,UZK,LZSK,LZPK,CI,CGS,CGP,KE,XE
__constant__ float c_lo[21] = {0.1f, 0.0f, 0.0f, 10.0f, 10.0f, 50.0f, 10.0f, 50.0f,
                               0.0f, 0.0f, 0.0f, 5.0f, 1.0f, 0.1f, 0.01f, 0.001f,
                               0.5f, 0.95f, 0.98f, 0.0f, 0.0f};
__constant__ float c_hi[21] = {1.2f, 0.1f, 0.3f, 100.0f, 100.0f, 400.0f, 100.0f, 1000.0f,
                               0.3f, 0.5f, 0.1f, 350.0f, 4.0f, 0.5f, 0.35f, 0.05f,
                               0.9f, 0.998f, 0.998f, 1.0f, 0.5f};

// Precomputed per-basin parameters (everything loop-invariant).
struct Prm {
    float kc, pctim, adimp;
    float uztwm, lztwm, uzfwm;
    float lzfsm, lzfpm;
    float pfree, riva;
    float zperc, rexp, uzk;
    float lzsk, lzpk;
    float ci, cgs, cgp;
    float inv_uztwm, inv_sum_utlt, inv_lztwm;
    float sum_uzm, inv_uzfwm;
    float pbase, sum_lzm, inv_sum_lzm, sum_lzf, cf2;  // cf2 = 2*lzfpm/(lzfsm+lzfpm)
    float inv_lzfpm, inv_lzfsm;
    float parea, omci, omcgs, omcgp;
    float c1, c2, c3;
};

struct St {
    float auztw, alztw, uztw, uzfw, lztw, lzfs, lzfp;
    float qs, qi, qgs, qgp, mq;
};

__device__ __forceinline__ void load_prm(const float* __restrict__ raw, int b, Prm& P) {
    float pr[21];
#pragma unroll
    for (int i = 0; i < 21; ++i)
        pr[i] = fmaf(raw[b * 21 + i], c_hi[i] - c_lo[i], c_lo[i]);

    P.kc = pr[0];  P.pctim = pr[1];  P.adimp = pr[2];
    P.uztwm = pr[3]; P.uzfwm = pr[4]; P.lztwm = pr[5];
    P.lzfsm = pr[6]; P.lzfpm = pr[7];
    P.pfree = pr[9]; P.riva = pr[10];
    P.zperc = pr[11]; P.rexp = pr[12]; P.uzk = pr[13];
    P.lzsk = pr[14]; P.lzpk = pr[15];
    P.ci = pr[16]; P.cgs = pr[17]; P.cgp = pr[18];
    float ke = pr[19], xe = pr[20];

    P.inv_uztwm    = 1.0f / P.uztwm;
    P.inv_sum_utlt = 1.0f / (P.uztwm + P.lztwm);
    P.inv_lztwm    = 1.0f / P.lztwm;
    P.sum_uzm      = P.uztwm + P.uzfwm;
    P.inv_uzfwm    = 1.0f / P.uzfwm;
    P.pbase        = P.lzfsm * P.lzsk + P.lzfpm * P.lzpk;
    P.sum_lzm      = P.lzfsm + P.lzfpm + P.lztwm;
    P.inv_sum_lzm  = 1.0f / P.sum_lzm;
    P.sum_lzf      = P.lzfsm + P.lzfpm;
    P.cf2          = 2.0f * P.lzfpm / P.sum_lzf;
    P.inv_lzfpm    = 1.0f / P.lzfpm;
    P.inv_lzfsm    = 1.0f / P.lzfsm;
    P.parea        = 1.0f - P.pctim - P.adimp;
    P.omci  = 1.0f - P.ci;
    P.omcgs = 1.0f - P.cgs;
    P.omcgp = 1.0f - P.cgp;
    const float dtm = 0.5f;
    float denom = ke * (1.0f - xe) + dtm;
    float inv_denom = 1.0f / denom;
    P.c1 = (ke * xe + dtm) * inv_denom;
    P.c2 = (dtm - ke * xe) * inv_denom;
    P.c3 = (ke * (1.0f - xe) - dtm) * inv_denom;
}

__device__ __forceinline__ void sac_step(const Prm& P, St& S,
                                         float p_raw, float e_raw,
                                         float& o2_out, float& et_out) {
    float p = fmaxf(p_raw, 0.0f);
    float e = e_raw;
    if (!isfinite(e)) e = 0.0f;
    e = fmaxf(e, 0.0f);
    float ep = P.kc * e;

    float roimp = P.pctim * p;
    float ae2 = P.pctim * ep;
    float ae1 = fminf(S.auztw, ep * (S.auztw * P.inv_uztwm));
    float ae3 = fmaxf((ep - ae1) * (S.alztw * P.inv_sum_utlt), 0.0f);
    float pav = fmaxf(p - (P.uztwm - (S.auztw - ae1)), 0.0f);
    float adsur = fmaxf(pav * ((S.alztw - ae3) * P.inv_lztwm), 0.0f);
    float tmpA = pav - adsur + (S.alztw - ae3);
    float ars = fmaxf(tmpA - P.lztwm, 0.0f);
    S.auztw = fmaxf(fminf(P.uztwm, S.auztw - ae1 + p), 0.0f);
    S.alztw = fmaxf(fminf(P.lztwm, tmpA), 0.0f);

    float e1 = fminf(S.uztw, ep * (S.uztw * P.inv_uztwm));
    float e2 = fmaxf(fminf(S.uzfw, ep - e1), 0.0f);
    float e3 = fmaxf((ep - e1 - e2) * (S.lztw * P.inv_sum_utlt), 0.0f);
    float lt1 = fmaxf(S.lztw - e3, 0.0f);
    float e4 = P.riva * ep;
    float et = ae2 + ae1 + ae3 + e1 + e2 + e3 + e4;

    float x = p + (S.uztw + S.uzfw - e1 - e2);
    float rs = fmaxf(x - P.sum_uzm, 0.0f) * P.parea;
    float ut = fmaxf(fminf(P.uztwm, S.uztw - e1 + p), 0.0f);
    float uf = fmaxf(fminf(P.uzfwm, x - ut), 0.0f);
    float ri = uf * P.uzk;
    uf = fmaxf(uf - ri, 0.0f);

    float ss = S.lzfs + S.lzfp + lt1;
    float defr = fmaxf(1.0f - ss * P.inv_sum_lzm, 0.0f);
    float perc = P.pbase * (1.0f + P.zperc * __powf(defr, P.rexp)) * uf * P.inv_uzfwm;
    float rate = fmaxf(fminf(perc, P.sum_lzm - ss), 0.0f);
    uf = fmaxf(uf - rate, 0.0f);

    float fx = fmaxf(fminf(P.sum_lzf - (S.lzfs + S.lzfp),
                           fmaxf(rate - (P.lztwm - lt1), rate * P.pfree)), 0.0f);
    float perct = rate - fx;
    float ca = 1.0f - S.lzfp * P.inv_lzfpm;
    float cb = 1.0f - S.lzfs * P.inv_lzfsm;
    float coef = fminf(P.cf2 * __fdividef(ca, ca + cb), 1.0f);
    float percp = fmaxf(fminf(P.lzfpm - S.lzfp,
                              fmaxf(fx - (P.lzfsm - S.lzfs), coef * fx)), 0.0f);
    float percs = fmaxf(fx - percp, 0.0f);

    float lt = fminf(lt1 + perct, P.lztwm);
    float ls = S.lzfs + percs;
    float lp = S.lzfp + percp;
    float rgs = ls * P.lzsk;
    ls = fmaxf(ls - rgs, 0.0f);
    float rgp = lp * P.lzpk;
    lp = fmaxf(lp - rgp, 0.0f);

    float rs_tot = roimp + adsur * P.adimp + ars * P.adimp + rs;
    float i1 = S.qs + S.qi + S.qgs + S.qgp;
    S.qs  = rs_tot;
    S.qi  = P.ci  * S.qi  + P.omci  * (ri  * P.parea);
    S.qgs = P.cgs * S.qgs + P.omcgs * (rgs * P.parea);
    S.qgp = P.cgp * S.qgp + P.omcgp * (rgp * P.parea);
    float i2 = S.qs + S.qi + S.qgs + S.qgp;
    float o2 = P.c1 * i1 + P.c2 * i2 + P.c3 * S.mq;
    S.mq = o2;

    S.uztw = ut; S.uzfw = uf; S.lztw = lt; S.lzfs = ls; S.lzfp = lp;

    o2_out = o2;
    et_out = et;
}

__device__ __forceinline__ void init_state(St& S) {
    S.auztw = S.alztw = S.uztw = S.uzfw = S.lztw = 0.01f;
    S.lzfs = S.lzfp = 0.01f;
    S.qs = S.qi = S.qgs = S.qgp = S.mq = 0.01f;
}

// Two basins per thread: two independent dependency chains interleaved in one
// instruction stream -> ~2x issue-slot utilization on a latency-bound chain.
__global__ void __launch_bounds__(128, 1) sac_kernel2(
    const float4* __restrict__ pe4,     // [T, B/2] of (p0,e0,p1,e1)
    const float*  __restrict__ raw,     // [B, 21]
    float*        __restrict__ out,     // [2, T-NWARM, B]
    int T, int B)
{
    int tid = blockIdx.x * blockDim.x + threadIdx.x;
    int half = B >> 1;                 // B is even (10000)
    if (tid >= half) return;
    int b0 = 2 * tid;
    int b1 = b0 + 1;

    Prm P0, P1;
    load_prm(raw, b0, P0);
    load_prm(raw, b1, P1);

    St S0, S1;
    init_state(S0);
    init_state(S1);

    const int TOUT = T - NWARM;
    float* __restrict__ outQ = out;                       // [TOUT, B]
    float* __restrict__ outE = out + (size_t)TOUT * B;    // [TOUT, B]

    float4 cur = pe4[tid];   // t = 0
    for (int t = 0; t < T; ++t) {
        // prefetch next timestep (keeps DRAM latency off the critical path)
        float4 nxt = (t + 1 < T) ? pe4[(size_t)(t + 1) * half + tid] : cur;

        float o2a, eta, o2b, etb;
        sac_step(P0, S0, cur.x, cur.y, o2a, eta);
        sac_step(P1, S1, cur.z, cur.w, o2b, etb);

        if (t >= NWARM) {
            size_t to = (size_t)(t - NWARM) * B + b0;
            *(float2*)(outQ + to) = make_float2(o2a, o2b);
            *(float2*)(outE + to) = make_float2(eta, etb);
        }
        cur = nxt;
    }
}

extern "C" void kernel_launch(void* const* d_in, const int* in_sizes, int n_in,
                              void* d_out, int out_size) {
    const float* pe     = (const float*)d_in[0];   // [T, B, 2] f32
    const float* params = (const float*)d_in[1];   // [B, 21]  f32
    int B = in_sizes[1] / 21;
    int T = in_sizes[0] / (2 * B);
    int half = B / 2;
    int threads = 128;
    int blocks = (half + threads - 1) / threads;
    sac_kernel2<<<blocks, threads>>>((const float4*)pe, params, (float*)d_out, T, B);
}

// round 4
// speedup vs baseline: 2.6002x; 2.6002x over previous
#include <cuda_runtime.h>

#define NWARM 365
#define PFD 8   // prefetch depth (register pipeline of future timesteps)

// PARAM_RANGES lo/hi, order: KC,PCTIM,ADIMP,UZTWM,UZFWM,LZTWM,LZFSM,LZFPM,RSERV,
// PFREE,RIVA,ZPERC,REXP,UZK,LZSK,LZPK,CI,CGS,CGP,KE,XE
__constant__ float c_lo[21] = {0.1f, 0.0f, 0.0f, 10.0f, 10.0f, 50.0f, 10.0f, 50.0f,
                               0.0f, 0.0f, 0.0f, 5.0f, 1.0f, 0.1f, 0.01f, 0.001f,
                               0.5f, 0.95f, 0.98f, 0.0f, 0.0f};
__constant__ float c_hi[21] = {1.2f, 0.1f, 0.3f, 100.0f, 100.0f, 400.0f, 100.0f, 1000.0f,
                               0.3f, 0.5f, 0.1f, 350.0f, 4.0f, 0.5f, 0.35f, 0.05f,
                               0.9f, 0.998f, 0.998f, 1.0f, 0.5f};

__global__ void __launch_bounds__(128, 1) sac_kernel(
    const float2* __restrict__ pe,      // [T, B] of (prcp, pet)
    const float*  __restrict__ raw,     // [B, 21] raw params in [0.01, 0.99]
    float*        __restrict__ out,     // [2, T-NWARM, B]
    int T, int B)
{
    int b = blockIdx.x * blockDim.x + threadIdx.x;
    if (b >= B) return;

    // ---- load + scale parameters ----
    float pr[21];
#pragma unroll
    for (int i = 0; i < 21; ++i)
        pr[i] = fmaf(raw[b * 21 + i], c_hi[i] - c_lo[i], c_lo[i]);

    const float kc = pr[0],  pctim = pr[1],  adimp = pr[2];
    const float uztwm = pr[3], uzfwm = pr[4], lztwm = pr[5];
    const float lzfsm = pr[6], lzfpm = pr[7];
    const float pfree = pr[9], riva = pr[10];
    const float zperc = pr[11], rexp = pr[12], uzk = pr[13];
    const float lzsk = pr[14], lzpk = pr[15];
    const float ci = pr[16], cgs = pr[17], cgp = pr[18];
    const float ke = pr[19], xe = pr[20];

    // ---- loop-invariant combos ----
    const float inv_uztwm    = 1.0f / uztwm;
    const float inv_sum_utlt = 1.0f / (uztwm + lztwm);
    const float inv_lztwm    = 1.0f / lztwm;
    const float sum_uzm      = uztwm + uzfwm;
    const float inv_uzfwm    = 1.0f / uzfwm;
    const float pbase        = lzfsm * lzsk + lzfpm * lzpk;
    const float sum_lzm      = lzfsm + lzfpm + lztwm;
    const float inv_sum_lzm  = 1.0f / sum_lzm;
    const float sum_lzf      = lzfsm + lzfpm;
    const float cf2          = 2.0f * lzfpm / sum_lzf;
    const float inv_lzfpm    = 1.0f / lzfpm;
    const float inv_lzfsm    = 1.0f / lzfsm;
    const float parea        = 1.0f - pctim - adimp;
    const float omci  = 1.0f - ci;
    const float omcgs = 1.0f - cgs;
    const float omcgp = 1.0f - cgp;
    const float dtm   = 0.5f;
    const float denom = ke * (1.0f - xe) + dtm;
    const float inv_denom = 1.0f / denom;
    const float c1 = (ke * xe + dtm) * inv_denom;
    const float c2 = (dtm - ke * xe) * inv_denom;
    const float c3 = (ke * (1.0f - xe) - dtm) * inv_denom;

    // ---- state ----
    float auztw = 0.01f, alztw = 0.01f, uztw = 0.01f, uzfw = 0.01f, lztw = 0.01f;
    float lzfs = 0.01f, lzfp = 0.01f;
    float qs = 0.01f, qi = 0.01f, qgs = 0.01f, qgp = 0.01f, mq = 0.01f;

    const int TOUT = T - NWARM;
    float* __restrict__ outQ = out;                       // [TOUT, B]
    float* __restrict__ outE = out + (size_t)TOUT * B;    // [TOUT, B]

    // one-step body as a macro so every use gets fully inlined with static regs
#define SAC_BODY(PEV, TT)                                                        \
    {                                                                            \
        float p = fmaxf((PEV).x, 0.0f);                                          \
        float e = (PEV).y;                                                       \
        if (!isfinite(e)) e = 0.0f;                                              \
        e = fmaxf(e, 0.0f);                                                      \
        float ep = kc * e;                                                       \
        float roimp = pctim * p;                                                 \
        float ae2 = pctim * ep;                                                  \
        float ae1 = fminf(auztw, ep * (auztw * inv_uztwm));                      \
        float ae3 = fmaxf((ep - ae1) * (alztw * inv_sum_utlt), 0.0f);            \
        float pav = fmaxf(p - (uztwm - (auztw - ae1)), 0.0f);                    \
        float adsur = fmaxf(pav * ((alztw - ae3) * inv_lztwm), 0.0f);            \
        float tmpA = pav - adsur + (alztw - ae3);                                \
        float ars = fmaxf(tmpA - lztwm, 0.0f);                                   \
        auztw = fmaxf(fminf(uztwm, auztw - ae1 + p), 0.0f);                      \
        alztw = fmaxf(fminf(lztwm, tmpA), 0.0f);                                 \
        float e1 = fminf(uztw, ep * (uztw * inv_uztwm));                         \
        float e2 = fmaxf(fminf(uzfw, ep - e1), 0.0f);                            \
        float e3 = fmaxf((ep - e1 - e2) * (lztw * inv_sum_utlt), 0.0f);          \
        float lt1 = fmaxf(lztw - e3, 0.0f);                                      \
        float e4 = riva * ep;                                                    \
        float et = ae2 + ae1 + ae3 + e1 + e2 + e3 + e4;                          \
        float x = p + (uztw + uzfw - e1 - e2);                                   \
        float rs = fmaxf(x - sum_uzm, 0.0f) * parea;                             \
        float ut = fmaxf(fminf(uztwm, uztw - e1 + p), 0.0f);                     \
        float uf = fmaxf(fminf(uzfwm, x - ut), 0.0f);                            \
        float ri = uf * uzk;                                                     \
        uf = fmaxf(uf - ri, 0.0f);                                               \
        float ss = lzfs + lzfp + lt1;                                            \
        float defr = fmaxf(1.0f - ss * inv_sum_lzm, 0.0f);                       \
        float perc = pbase * (1.0f + zperc * __powf(defr, rexp)) * uf * inv_uzfwm; \
        float rate = fmaxf(fminf(perc, sum_lzm - ss), 0.0f);                     \
        uf = fmaxf(uf - rate, 0.0f);                                             \
        float fx = fmaxf(fminf(sum_lzf - (lzfs + lzfp),                          \
                               fmaxf(rate - (lztwm - lt1), rate * pfree)), 0.0f);\
        float perct = rate - fx;                                                 \
        float ca = 1.0f - lzfp * inv_lzfpm;                                      \
        float cb = 1.0f - lzfs * inv_lzfsm;                                      \
        float coef = fminf(cf2 * __fdividef(ca, ca + cb), 1.0f);                 \
        float percp = fmaxf(fminf(lzfpm - lzfp,                                  \
                                  fmaxf(fx - (lzfsm - lzfs), coef * fx)), 0.0f); \
        float percs = fmaxf(fx - percp, 0.0f);                                   \
        float lt = fminf(lt1 + perct, lztwm);                                    \
        float ls = lzfs + percs;                                                 \
        float lp = lzfp + percp;                                                 \
        float rgs = ls * lzsk;                                                   \
        ls = fmaxf(ls - rgs, 0.0f);                                              \
        float rgp = lp * lzpk;                                                   \
        lp = fmaxf(lp - rgp, 0.0f);                                              \
        float rs_tot = roimp + adsur * adimp + ars * adimp + rs;                 \
        float i1 = qs + qi + qgs + qgp;                                          \
        qs  = rs_tot;                                                            \
        qi  = ci  * qi  + omci  * (ri  * parea);                                 \
        qgs = cgs * qgs + omcgs * (rgs * parea);                                 \
        qgp = cgp * qgp + omcgp * (rgp * parea);                                 \
        float i2 = qs + qi + qgs + qgp;                                          \
        float o2 = c1 * i1 + c2 * i2 + c3 * mq;                                  \
        mq = o2;                                                                 \
        uztw = ut; uzfw = uf; lztw = lt; lzfs = ls; lzfp = lp;                   \
        if ((TT) >= NWARM) {                                                     \
            size_t to = (size_t)((TT) - NWARM) * B + b;                          \
            outQ[to] = o2;                                                       \
            outE[to] = et;                                                       \
        }                                                                        \
    }

    // ---- register pipeline: PFD timesteps in flight ----
    float2 buf[PFD];
#pragma unroll
    for (int d = 0; d < PFD; ++d) {
        int idx = d < T ? d : T - 1;
        buf[d] = __ldcs(&pe[(size_t)idx * B + b]);
    }

    int t = 0;
    // main loop: full chunks of PFD; load for t+j+PFD issued while processing t+j
    for (; t + PFD <= T; t += PFD) {
#pragma unroll
        for (int j = 0; j < PFD; ++j) {
            int tl = t + j + PFD;
            float2 nxt = __ldcs(&pe[(size_t)(tl < T ? tl : T - 1) * B + b]);
            SAC_BODY(buf[j], t + j);
            buf[j] = nxt;
        }
    }
    // tail (< PFD steps), static buffer indices preserved
#pragma unroll
    for (int j = 0; j < PFD; ++j) {
        int tt = t + j;
        if (tt < T) {
            SAC_BODY(buf[j], tt);
        }
    }
#undef SAC_BODY
}

extern "C" void kernel_launch(void* const* d_in, const int* in_sizes, int n_in,
                              void* d_out, int out_size) {
    const float* pe     = (const float*)d_in[0];   // [T, B, 2] f32
    const float* params = (const float*)d_in[1];   // [B, 21]  f32
    int B = in_sizes[1] / 21;
    int T = in_sizes[0] / (2 * B);
    int threads = 128;
    int blocks = (B + threads - 1) / threads;
    sac_kernel<<<blocks, threads>>>((const float2*)pe, params, (float*)d_out, T, B);
}

// round 5
// speedup vs baseline: 2.7605x; 1.0616x over previous
#include <cuda_runtime.h>

#define NWARM 365
#define PFD 8   // prefetch depth (register pipeline of future timesteps)

// PARAM_RANGES lo/hi, order: KC,PCTIM,ADIMP,UZTWM,UZFWM,LZTWM,LZFSM,LZFPM,RSERV,
// PFREE,RIVA,ZPERC,REXP,UZK,LZSK,LZPK,CI,CGS,CGP,KE,XE
__constant__ float c_lo[21] = {0.1f, 0.0f, 0.0f, 10.0f, 10.0f, 50.0f, 10.0f, 50.0f,
                               0.0f, 0.0f, 0.0f, 5.0f, 1.0f, 0.1f, 0.01f, 0.001f,
                               0.5f, 0.95f, 0.98f, 0.0f, 0.0f};
__constant__ float c_hi[21] = {1.2f, 0.1f, 0.3f, 100.0f, 100.0f, 400.0f, 100.0f, 1000.0f,
                               0.3f, 0.5f, 0.1f, 350.0f, 4.0f, 0.5f, 0.35f, 0.05f,
                               0.9f, 0.998f, 0.998f, 1.0f, 0.5f};

__global__ void __launch_bounds__(128, 1) sac_kernel(
    const float2* __restrict__ pe,      // [T, B] of (prcp, pet)
    const float*  __restrict__ raw,     // [B, 21] raw params in [0.01, 0.99]
    float*        __restrict__ out,     // [2, T-NWARM, B]
    int T, int B)
{
    int b = blockIdx.x * blockDim.x + threadIdx.x;
    if (b >= B) return;

    // ---- load + scale parameters ----
    float pr[21];
#pragma unroll
    for (int i = 0; i < 21; ++i)
        pr[i] = fmaf(raw[b * 21 + i], c_hi[i] - c_lo[i], c_lo[i]);

    const float kc = pr[0],  pctim = pr[1],  adimp = pr[2];
    const float uztwm = pr[3], uzfwm = pr[4], lztwm = pr[5];
    const float lzfsm = pr[6], lzfpm = pr[7];
    const float pfree = pr[9], riva = pr[10];
    const float zperc = pr[11], rexp = pr[12], uzk = pr[13];
    const float lzsk = pr[14], lzpk = pr[15];
    const float ci = pr[16], cgs = pr[17], cgp = pr[18];
    const float ke = pr[19], xe = pr[20];

    // ---- loop-invariant combos ----
    const float inv_uztwm    = 1.0f / uztwm;
    const float inv_sum_utlt = 1.0f / (uztwm + lztwm);
    const float inv_lztwm    = 1.0f / lztwm;
    const float sum_uzm      = uztwm + uzfwm;
    const float inv_uzfwm    = 1.0f / uzfwm;
    const float pbase        = lzfsm * lzsk + lzfpm * lzpk;
    const float sum_lzm      = lzfsm + lzfpm + lztwm;
    const float inv_sum_lzm  = 1.0f / sum_lzm;
    const float sum_lzf      = lzfsm + lzfpm;
    const float cf2          = 2.0f * lzfpm / sum_lzf;
    const float inv_lzfpm    = 1.0f / lzfpm;
    const float inv_lzfsm    = 1.0f / lzfsm;
    const float parea        = 1.0f - pctim - adimp;
    const float omlzsk = 1.0f - lzsk;         // decay factors (replace sub+max)
    const float omlzpk = 1.0f - lzpk;
    // folded IIR input gains: (1-ci)*parea etc.
    const float gi  = (1.0f - ci)  * parea;
    const float ggs = (1.0f - cgs) * parea;
    const float ggp = (1.0f - cgp) * parea;
    const float dtm   = 0.5f;
    const float denom = ke * (1.0f - xe) + dtm;
    const float inv_denom = 1.0f / denom;
    const float c1 = (ke * xe + dtm) * inv_denom;
    const float c2 = (dtm - ke * xe) * inv_denom;
    const float c3 = (ke * (1.0f - xe) - dtm) * inv_denom;
    const float pbase_div_uzfwm = pbase * inv_uzfwm;

    // ---- state ----
    float auztw = 0.01f, alztw = 0.01f, uztw = 0.01f, uzfw = 0.01f, lztw = 0.01f;
    float lzfs = 0.01f, lzfp = 0.01f;
    float qs = 0.01f, qi = 0.01f, qgs = 0.01f, qgp = 0.01f, mq = 0.01f;

    const int TOUT = T - NWARM;
    float* __restrict__ outQ = out;                       // [TOUT, B]
    float* __restrict__ outE = out + (size_t)TOUT * B;    // [TOUT, B]

    // One-step body. Clamps that are provably inactive under the state
    // invariants (0 <= state <= capacity; ep <= 7.2 < uztwm+lztwm) are removed.
#define SAC_BODY(PEV, TT)                                                        \
    {                                                                            \
        float p = fmaxf((PEV).x, 0.0f);                                          \
        float e = fmaxf((PEV).y, 0.0f);      /* fmaxf(NaN,0)=0 => nan_to_num */  \
        float ep = kc * e;                                                       \
        float roimp = pctim * p;                                                 \
        float ae2 = pctim * ep;                                                  \
        /* ADIMP store */                                                        \
        float ae1 = fminf(auztw, ep * (auztw * inv_uztwm));                      \
        float ae3 = (ep - ae1) * (alztw * inv_sum_utlt);      /* >= 0 */         \
        float pav = fmaxf(p - (uztwm - (auztw - ae1)), 0.0f);                    \
        float alz_ae3 = alztw - ae3;                          /* >= 0 */         \
        float adsur = pav * (alz_ae3 * inv_lztwm);            /* >= 0 */         \
        float tmpA = pav - adsur + alz_ae3;                   /* >= 0 */         \
        float ars = fmaxf(tmpA - lztwm, 0.0f);                                   \
        auztw = fminf(uztwm, auztw - ae1 + p);                                   \
        alztw = fminf(lztwm, tmpA);                                              \
        /* UZ evap */                                                            \
        float e1 = fminf(uztw, ep * (uztw * inv_uztwm));                         \
        float e2 = fminf(uzfw, ep - e1);                      /* >= 0 */         \
        float e3 = (ep - e1 - e2) * (lztw * inv_sum_utlt);    /* >= 0 */         \
        float lt1 = lztw - e3;                                /* >= 0 */         \
        float et = ae2 + ae1 + ae3 + e1 + e2 + e3 + riva * ep;                   \
        /* UZ balance */                                                         \
        float x = p + (uztw + uzfw - e1 - e2);                                   \
        float rs = fmaxf(x - sum_uzm, 0.0f) * parea;                             \
        float ut = fminf(uztwm, uztw - e1 + p);               /* >= 0 */         \
        float uf = fminf(uzfwm, x - ut);                      /* >= 0 */         \
        float ri = uf * uzk;                                                     \
        uf = uf - ri;                                         /* >= 0 */         \
        /* percolation */                                                        \
        float ss = lzfs + lzfp + lt1;                                            \
        float defr = fmaxf(1.0f - ss * inv_sum_lzm, 0.0f);                       \
        float perc = pbase_div_uzfwm * (1.0f + zperc * __powf(defr, rexp)) * uf; \
        float rate = fminf(perc, sum_lzm - ss);               /* >= 0 */         \
        uf = fmaxf(uf - rate, 0.0f);                                             \
        float fx = fminf(sum_lzf - (lzfs + lzfp),                                \
                         fmaxf(rate - (lztwm - lt1), rate * pfree)); /* >= 0 */  \
        float perct = rate - fx;                                                 \
        float ca = 1.0f - lzfp * inv_lzfpm;                                      \
        float cb = 1.0f - lzfs * inv_lzfsm;                                      \
        float coef = fminf(cf2 * __fdividef(ca, ca + cb), 1.0f);                 \
        float percp = fmaxf(fminf(lzfpm - lzfp,                                  \
                                  fmaxf(fx - (lzfsm - lzfs), coef * fx)), 0.0f); \
        float percs = fmaxf(fx - percp, 0.0f);                                   \
        /* LZ update + decay (decay leaves >= 0) */                              \
        float lt = fminf(lt1 + perct, lztwm);                                    \
        float ls = lzfs + percs;                                                 \
        float lp = lzfp + percp;                                                 \
        float rgs = ls * lzsk;                                                   \
        float rgp = lp * lzpk;                                                   \
        ls = ls * omlzsk;                                                        \
        lp = lp * omlzpk;                                                        \
        /* routing */                                                            \
        float rs_tot = roimp + (adsur + ars) * adimp + rs;                       \
        float i1 = qs + qi + qgs + qgp;                                          \
        qs  = rs_tot;                                                            \
        qi  = ci  * qi  + gi  * ri;                                              \
        qgs = cgs * qgs + ggs * rgs;                                             \
        qgp = cgp * qgp + ggp * rgp;                                             \
        float i2 = qs + qi + qgs + qgp;                                          \
        float o2 = c1 * i1 + c2 * i2 + c3 * mq;                                  \
        mq = o2;                                                                 \
        uztw = ut; uzfw = uf; lztw = lt; lzfs = ls; lzfp = lp;                   \
        if ((TT) >= NWARM) {                                                     \
            size_t to = (size_t)((TT) - NWARM) * B + b;                          \
            outQ[to] = o2;                                                       \
            outE[to] = et;                                                       \
        }                                                                        \
    }

    // ---- register pipeline: PFD timesteps in flight ----
    float2 buf[PFD];
#pragma unroll
    for (int d = 0; d < PFD; ++d) {
        int idx = d < T ? d : T - 1;
        buf[d] = __ldcs(&pe[(size_t)idx * B + b]);
    }

    int t = 0;
    for (; t + PFD <= T; t += PFD) {
#pragma unroll
        for (int j = 0; j < PFD; ++j) {
            int tl = t + j + PFD;
            float2 nxt = __ldcs(&pe[(size_t)(tl < T ? tl : T - 1) * B + b]);
            SAC_BODY(buf[j], t + j);
            buf[j] = nxt;
        }
    }
#pragma unroll
    for (int j = 0; j < PFD; ++j) {
        int tt = t + j;
        if (tt < T) {
            SAC_BODY(buf[j], tt);
        }
    }
#undef SAC_BODY
}

extern "C" void kernel_launch(void* const* d_in, const int* in_sizes, int n_in,
                              void* d_out, int out_size) {
    const float* pe     = (const float*)d_in[0];   // [T, B, 2] f32
    const float* params = (const float*)d_in[1];   // [B, 21]  f32
    int B = in_sizes[1] / 21;
    int T = in_sizes[0] / (2 * B);
    int threads = 128;
    int blocks = (B + threads - 1) / threads;
    sac_kernel<<<blocks, threads>>>((const float2*)pe, params, (float*)d_out, T, B);
}